// round 3
// baseline (speedup 1.0000x reference)
#include <cuda_runtime.h>
#include <cuda_bf16.h>
#include <math.h>

#define Bn 64
#define Nn 1024
#define Dn 64
#define Mr 64          // query rows per CTA
#define NB 128         // key block
#define THREADS 256
#define SA 72          // elem stride for 64-col bf16 tiles (conflict-free)
#define SP 136         // elem stride for 128-col bf16 tiles

// ---- smem byte offsets ----
#define SM_SPART 0          // float[4][64] partial row sums
#define SM_SINV  1024       // float[64] 1/rowsum
#define U        2048
// pass S union layout
#define B_QHI (U)
#define B_QLO (U + 9216)
#define B_KHI (U + 18432)
#define B_KLO (U + 36864)
// pass PV union layout (overwrites pass-S buffers)
#define C_PHI (U)
#define C_PLO (U + 17408)
#define C_VTH (U + 34816)
#define C_VTL (U + 52224)
#define SM_TOTAL (U + 69632)

__device__ __forceinline__ void mma16816(float* c, const unsigned* a, const unsigned* b) {
    asm volatile(
        "mma.sync.aligned.m16n8k16.row.col.f32.bf16.bf16.f32 "
        "{%0,%1,%2,%3}, {%4,%5,%6,%7}, {%8,%9}, {%0,%1,%2,%3};"
        : "+f"(c[0]), "+f"(c[1]), "+f"(c[2]), "+f"(c[3])
        : "r"(a[0]), "r"(a[1]), "r"(a[2]), "r"(a[3]), "r"(b[0]), "r"(b[1]));
}

// split 4 floats into bf16 hi/lo pairs (packed bf16x2)
__device__ __forceinline__ void split4(float4 a, unsigned& h0, unsigned& h1,
                                       unsigned& l0, unsigned& l1) {
    __nv_bfloat162 H0 = __floats2bfloat162_rn(a.x, a.y);
    __nv_bfloat162 H1 = __floats2bfloat162_rn(a.z, a.w);
    float2 f0 = __bfloat1622float2(H0);
    float2 f1 = __bfloat1622float2(H1);
    __nv_bfloat162 L0 = __floats2bfloat162_rn(a.x - f0.x, a.y - f0.y);
    __nv_bfloat162 L1 = __floats2bfloat162_rn(a.z - f1.x, a.w - f1.y);
    h0 = *(unsigned*)&H0; h1 = *(unsigned*)&H1;
    l0 = *(unsigned*)&L0; l1 = *(unsigned*)&L1;
}

__global__ __launch_bounds__(THREADS)
void sdpa_hmma_kernel(const float* __restrict__ q,
                      const float* __restrict__ k,
                      const float* __restrict__ v,
                      const float* __restrict__ qs,
                      const float* __restrict__ ks,
                      float* __restrict__ out,
                      float* __restrict__ attn,
                      float* __restrict__ score)
{
    extern __shared__ char smb[];
    const int tid  = threadIdx.x;
    const int wid  = tid >> 5;
    const int lane = tid & 31;
    const int b    = blockIdx.y;
    const int row0 = blockIdx.x * Mr;
    const size_t bND = (size_t)b * Nn * Dn;
    const size_t bNN = (size_t)b * Nn * Nn;

    float* spart = (float*)(smb + SM_SPART);
    float* sinv  = (float*)(smb + SM_SINV);

    // ================= Pass A: Qf = q + q_sem -> bf16 hi/lo [64][SA] =================
    {
        const float* qp  = q  + bND + (size_t)row0 * Dn;
        const float* qsp = qs + bND + (size_t)row0 * Dn;
        #pragma unroll
        for (int it = 0; it < 4; it++) {
            int idx = (tid + it * THREADS) * 4;
            float4 a = *(const float4*)(qp + idx);
            float4 s0 = *(const float4*)(qsp + idx);
            a.x += s0.x; a.y += s0.y; a.z += s0.z; a.w += s0.w;
            int r = idx >> 6, d = idx & 63;
            unsigned h0, h1, l0, l1; split4(a, h0, h1, l0, l1);
            char* p = smb + B_QHI + (r * SA + d) * 2;
            *(unsigned*)p = h0; *(unsigned*)(p + 4) = h1;
            char* pl = p + (B_QLO - B_QHI);
            *(unsigned*)pl = l0; *(unsigned*)(pl + 4) = l1;
        }
    }

    // ================= Pass S: scores + row sums =================
    const int mq = wid >> 2;      // 0..1 : rows mq*32 + 2 mfrags
    const int nq = wid & 3;       // 0..3 : cols nq*32 per key-block
    const int lq = lane >> 2;     // 0..7
    const int lr = lane & 3;      // 0..3
    float sreg[4] = {0.f, 0.f, 0.f, 0.f};

    for (int kb = 0; kb < Nn / NB; kb++) {
        __syncthreads();   // protect prior mma reads of K tile
        {
            const float* kp  = k  + bND + (size_t)(kb * NB) * Dn;
            const float* ksp = ks + bND + (size_t)(kb * NB) * Dn;
            #pragma unroll
            for (int it = 0; it < 8; it++) {
                int idx = (tid + it * THREADS) * 4;
                float4 a = *(const float4*)(kp + idx);
                float4 s0 = *(const float4*)(ksp + idx);
                a.x += s0.x; a.y += s0.y; a.z += s0.z; a.w += s0.w;
                int r = idx >> 6, d = idx & 63;
                unsigned h0, h1, l0, l1; split4(a, h0, h1, l0, l1);
                char* p = smb + B_KHI + (r * SA + d) * 2;
                *(unsigned*)p = h0; *(unsigned*)(p + 4) = h1;
                char* pl = p + (B_KLO - B_KHI);
                *(unsigned*)pl = l0; *(unsigned*)(pl + 4) = l1;
            }
        }
        __syncthreads();

        float acc[2][4][4];
        #pragma unroll
        for (int mf = 0; mf < 2; mf++)
            #pragma unroll
            for (int nf = 0; nf < 4; nf++)
                #pragma unroll
                for (int i = 0; i < 4; i++) acc[mf][nf][i] = 0.f;

        #pragma unroll
        for (int ksi = 0; ksi < 4; ksi++) {
            const int kc = ksi * 16 + lr * 2;
            unsigned ah[2][4], al[2][4];
            #pragma unroll
            for (int mf = 0; mf < 2; mf++) {
                int r = mq * 32 + mf * 16 + lq;
                const char* pa = smb + B_QHI + (r * SA + kc) * 2;
                ah[mf][0] = *(const unsigned*)(pa);
                ah[mf][1] = *(const unsigned*)(pa + 8 * SA * 2);
                ah[mf][2] = *(const unsigned*)(pa + 16);
                ah[mf][3] = *(const unsigned*)(pa + 8 * SA * 2 + 16);
                const char* pal = pa + (B_QLO - B_QHI);
                al[mf][0] = *(const unsigned*)(pal);
                al[mf][1] = *(const unsigned*)(pal + 8 * SA * 2);
                al[mf][2] = *(const unsigned*)(pal + 16);
                al[mf][3] = *(const unsigned*)(pal + 8 * SA * 2 + 16);
            }
            #pragma unroll
            for (int nf = 0; nf < 4; nf++) {
                int n = nq * 32 + nf * 8 + lq;
                const char* pb = smb + B_KHI + (n * SA + kc) * 2;
                unsigned bh[2], bl[2];
                bh[0] = *(const unsigned*)(pb);
                bh[1] = *(const unsigned*)(pb + 16);
                const char* pbl = pb + (B_KLO - B_KHI);
                bl[0] = *(const unsigned*)(pbl);
                bl[1] = *(const unsigned*)(pbl + 16);
                #pragma unroll
                for (int mf = 0; mf < 2; mf++) {
                    mma16816(acc[mf][nf], ah[mf], bh);
                    mma16816(acc[mf][nf], ah[mf], bl);
                    mma16816(acc[mf][nf], al[mf], bh);
                }
            }
        }

        // epilogue: scale, accumulate exp-sums, write attn_score
        #pragma unroll
        for (int mf = 0; mf < 2; mf++) {
            #pragma unroll
            for (int nf = 0; nf < 4; nf++) {
                float v0 = acc[mf][nf][0] * 0.125f;
                float v1 = acc[mf][nf][1] * 0.125f;
                float v2 = acc[mf][nf][2] * 0.125f;
                float v3 = acc[mf][nf][3] * 0.125f;
                sreg[mf * 2 + 0] += __expf(v0) + __expf(v1);
                sreg[mf * 2 + 1] += __expf(v2) + __expf(v3);
                const int r0 = row0 + mq * 32 + mf * 16 + lq;
                const int cc = kb * NB + nq * 32 + nf * 8 + lr * 2;
                float* g0 = score + bNN + (size_t)r0 * Nn + cc;
                g0[0] = v0; g0[1] = v1;
                float* g1 = g0 + (size_t)8 * Nn;
                g1[0] = v2; g1[1] = v3;
            }
        }
    }

    // combine partial sums (4 n-warps per row)
    #pragma unroll
    for (int i = 0; i < 4; i++) {
        sreg[i] += __shfl_xor_sync(0xffffffffu, sreg[i], 1);
        sreg[i] += __shfl_xor_sync(0xffffffffu, sreg[i], 2);
    }
    if (lr == 0) {
        #pragma unroll
        for (int mf = 0; mf < 2; mf++)
            #pragma unroll
            for (int hh = 0; hh < 2; hh++)
                spart[nq * 64 + mq * 32 + mf * 16 + hh * 8 + lq] = sreg[mf * 2 + hh];
    }
    __syncthreads();
    if (tid < 64)
        sinv[tid] = 1.0f / (spart[tid] + spart[64 + tid] + spart[128 + tid] + spart[192 + tid]);

    // ================= Pass PV: O = P @ V =================
    const int mq2 = wid >> 1;     // 0..3 : 16 rows
    const int nq2 = wid & 1;      // 0..1 : 32 cols
    float oacc[4][4];
    #pragma unroll
    for (int nf = 0; nf < 4; nf++)
        #pragma unroll
        for (int i = 0; i < 4; i++) oacc[nf][i] = 0.f;

    for (int kc = 0; kc < Nn / NB; kc++) {
        __syncthreads();   // protect prior frag reads (and pass-S buffers on kc=0)

        // build P hi/lo [64][SP] + write attn
        {
            const int pr  = tid >> 2;
            const int pcb = (tid & 3) * 32;
            const float iv = sinv[pr];
            const float* srow = score + bNN + (size_t)(row0 + pr) * Nn + kc * NB + pcb;
            float* arow = attn + bNN + (size_t)(row0 + pr) * Nn + kc * NB + pcb;
            #pragma unroll
            for (int j = 0; j < 8; j++) {
                float4 x = *(const float4*)(srow + j * 4);
                float4 p;
                p.x = __expf(x.x) * iv; p.y = __expf(x.y) * iv;
                p.z = __expf(x.z) * iv; p.w = __expf(x.w) * iv;
                *(float4*)(arow + j * 4) = p;
                unsigned h0, h1, l0, l1; split4(p, h0, h1, l0, l1);
                char* pp = smb + C_PHI + (pr * SP + pcb + j * 4) * 2;
                *(unsigned*)pp = h0; *(unsigned*)(pp + 4) = h1;
                char* pl = pp + (C_PLO - C_PHI);
                *(unsigned*)pl = l0; *(unsigned*)(pl + 4) = l1;
            }
        }
        // build V^T hi/lo [64 d][SP keys]
        {
            const int ky = tid >> 1;
            const int db = (tid & 1) * 32;
            const float* vp = v + bND + (size_t)(kc * NB + ky) * Dn + db;
            #pragma unroll
            for (int j = 0; j < 8; j++) {
                float4 x = *(const float4*)(vp + j * 4);
                float xe[4] = {x.x, x.y, x.z, x.w};
                #pragma unroll
                for (int e = 0; e < 4; e++) {
                    int d = db + j * 4 + e;
                    __nv_bfloat16 h = __float2bfloat16(xe[e]);
                    __nv_bfloat16 lo = __float2bfloat16(xe[e] - __bfloat162float(h));
                    *(__nv_bfloat16*)(smb + C_VTH + (d * SP + ky) * 2) = h;
                    *(__nv_bfloat16*)(smb + C_VTL + (d * SP + ky) * 2) = lo;
                }
            }
        }
        __syncthreads();

        #pragma unroll
        for (int ksi = 0; ksi < 8; ksi++) {
            const int kk = ksi * 16 + lr * 2;
            const int r = mq2 * 16 + lq;
            const char* pa = smb + C_PHI + (r * SP + kk) * 2;
            unsigned ah[4], al[4];
            ah[0] = *(const unsigned*)(pa);
            ah[1] = *(const unsigned*)(pa + 8 * SP * 2);
            ah[2] = *(const unsigned*)(pa + 16);
            ah[3] = *(const unsigned*)(pa + 8 * SP * 2 + 16);
            const char* pal = pa + (C_PLO - C_PHI);
            al[0] = *(const unsigned*)(pal);
            al[1] = *(const unsigned*)(pal + 8 * SP * 2);
            al[2] = *(const unsigned*)(pal + 16);
            al[3] = *(const unsigned*)(pal + 8 * SP * 2 + 16);
            #pragma unroll
            for (int nf = 0; nf < 4; nf++) {
                int n = nq2 * 32 + nf * 8 + lq;
                const char* pb = smb + C_VTH + (n * SP + kk) * 2;
                unsigned bh[2], bl[2];
                bh[0] = *(const unsigned*)(pb);
                bh[1] = *(const unsigned*)(pb + 16);
                const char* pbl = pb + (C_VTL - C_VTH);
                bl[0] = *(const unsigned*)(pbl);
                bl[1] = *(const unsigned*)(pbl + 16);
                mma16816(oacc[nf], ah, bh);
                mma16816(oacc[nf], ah, bl);
                mma16816(oacc[nf], al, bh);
            }
        }
    }

    // write O
    #pragma unroll
    for (int nf = 0; nf < 4; nf++) {
        const int r0 = row0 + mq2 * 16 + lq;
        const int c = nq2 * 32 + nf * 8 + lr * 2;
        float* o0 = out + bND + (size_t)r0 * Dn + c;
        o0[0] = oacc[nf][0]; o0[1] = oacc[nf][1];
        float* o1 = o0 + (size_t)8 * Dn;
        o1[0] = oacc[nf][2]; o1[1] = oacc[nf][3];
    }
}

extern "C" void kernel_launch(void* const* d_in, const int* in_sizes, int n_in,
                              void* d_out, int out_size) {
    const float* q  = (const float*)d_in[0];
    const float* k  = (const float*)d_in[1];
    const float* v  = (const float*)d_in[2];
    const float* qs = (const float*)d_in[3];
    const float* ks = (const float*)d_in[4];

    float* out   = (float*)d_out;
    float* attn  = out  + (size_t)Bn * Nn * Dn;
    float* score = attn + (size_t)Bn * Nn * Nn;

    cudaFuncSetAttribute(sdpa_hmma_kernel,
                         cudaFuncAttributeMaxDynamicSharedMemorySize, SM_TOTAL);

    dim3 grid(Nn / Mr, Bn);
    sdpa_hmma_kernel<<<grid, THREADS, SM_TOTAL>>>(q, k, v, qs, ks, out, attn, score);
}

// round 4
// speedup vs baseline: 1.5378x; 1.5378x over previous
#include <cuda_runtime.h>
#include <cuda_bf16.h>
#include <math.h>

#define Bn 64
#define Nn 1024
#define Dn 64
#define Mr 64          // query rows per CTA
#define NB 128         // key block
#define THREADS 256
#define SA 72          // elem stride for 64-col bf16 tiles (144B row, mult of 16)
#define SP 136         // elem stride for 128-col bf16 tiles (272B row, mult of 16)

// ---- smem byte offsets ----
#define SM_SPART 0          // float[4][64]
#define SM_SINV  1024       // float[64]
#define U        2048
// pass S layout
#define B_QHI (U)                 // 64*72*2  = 9216
#define B_QLO (U + 9216)
#define B_KHI (U + 18432)         // 128*72*2 = 18432
#define B_KLO (U + 36864)
// pass PV layout (reuses U region)
#define C_PHI (U)                 // 64*136*2 = 17408
#define C_PLO (U + 17408)
#define C_VTH (U + 34816)         // 128*72*2 = 18432 (natural [key][d])
#define C_VTL (U + 53248)
#define SM_TOTAL (U + 71680)      // 73728 B

__device__ __forceinline__ void mma16816(float* c, const unsigned* a, const unsigned* b) {
    asm volatile(
        "mma.sync.aligned.m16n8k16.row.col.f32.bf16.bf16.f32 "
        "{%0,%1,%2,%3}, {%4,%5,%6,%7}, {%8,%9}, {%0,%1,%2,%3};"
        : "+f"(c[0]), "+f"(c[1]), "+f"(c[2]), "+f"(c[3])
        : "r"(a[0]), "r"(a[1]), "r"(a[2]), "r"(a[3]), "r"(b[0]), "r"(b[1]));
}
__device__ __forceinline__ void ldsm4(unsigned* r, unsigned addr) {
    asm volatile("ldmatrix.sync.aligned.m8n8.x4.shared.b16 {%0,%1,%2,%3}, [%4];"
        : "=r"(r[0]), "=r"(r[1]), "=r"(r[2]), "=r"(r[3]) : "r"(addr));
}
__device__ __forceinline__ void ldsm4t(unsigned* r, unsigned addr) {
    asm volatile("ldmatrix.sync.aligned.m8n8.x4.trans.shared.b16 {%0,%1,%2,%3}, [%4];"
        : "=r"(r[0]), "=r"(r[1]), "=r"(r[2]), "=r"(r[3]) : "r"(addr));
}

// split 4 floats into bf16 hi/lo pairs (packed bf16x2)
__device__ __forceinline__ void split4(float4 a, unsigned& h0, unsigned& h1,
                                       unsigned& l0, unsigned& l1) {
    __nv_bfloat162 H0 = __floats2bfloat162_rn(a.x, a.y);
    __nv_bfloat162 H1 = __floats2bfloat162_rn(a.z, a.w);
    float2 f0 = __bfloat1622float2(H0);
    float2 f1 = __bfloat1622float2(H1);
    __nv_bfloat162 L0 = __floats2bfloat162_rn(a.x - f0.x, a.y - f0.y);
    __nv_bfloat162 L1 = __floats2bfloat162_rn(a.z - f1.x, a.w - f1.y);
    h0 = *(unsigned*)&H0; h1 = *(unsigned*)&H1;
    l0 = *(unsigned*)&L0; l1 = *(unsigned*)&L1;
}

__global__ __launch_bounds__(THREADS)
void sdpa_hmma_kernel(const float* __restrict__ q,
                      const float* __restrict__ k,
                      const float* __restrict__ v,
                      const float* __restrict__ qs,
                      const float* __restrict__ ks,
                      float* __restrict__ out,
                      float* __restrict__ attn,
                      float* __restrict__ score)
{
    extern __shared__ char smb[];
    const unsigned sb = (unsigned)__cvta_generic_to_shared(smb);
    const int tid  = threadIdx.x;
    const int wid  = tid >> 5;
    const int lane = tid & 31;
    const int b    = blockIdx.y;
    const int row0 = blockIdx.x * Mr;
    const size_t bND = (size_t)b * Nn * Dn;
    const size_t bNN = (size_t)b * Nn * Nn;

    float* spart = (float*)(smb + SM_SPART);
    float* sinv  = (float*)(smb + SM_SINV);

    // ================= Pass A: Qf = q + q_sem -> bf16 hi/lo [64][SA] =================
    {
        const float* qp  = q  + bND + (size_t)row0 * Dn;
        const float* qsp = qs + bND + (size_t)row0 * Dn;
        #pragma unroll
        for (int it = 0; it < 4; it++) {
            int idx = (tid + it * THREADS) * 4;
            float4 a = *(const float4*)(qp + idx);
            float4 s0 = *(const float4*)(qsp + idx);
            a.x += s0.x; a.y += s0.y; a.z += s0.z; a.w += s0.w;
            int r = idx >> 6, d = idx & 63;
            unsigned h0, h1, l0, l1; split4(a, h0, h1, l0, l1);
            char* p = smb + B_QHI + (r * SA + d) * 2;
            *(uint2*)p = make_uint2(h0, h1);
            *(uint2*)(p + (B_QLO - B_QHI)) = make_uint2(l0, l1);
        }
    }

    // ================= Pass S: scores + row sums =================
    const int mq = wid >> 2;      // 0..1
    const int nq = wid & 3;       // 0..3
    const int lq = lane >> 2;     // 0..7
    const int lr = lane & 3;      // 0..3
    float sreg[4] = {0.f, 0.f, 0.f, 0.f};

    // ldmatrix lane addressing (elements -> bytes *2)
    const unsigned a_lane = (unsigned)(((lane & 15) * SA + (lane >> 4) * 8) * 2);
    const unsigned b_lane = (unsigned)(((((lane >> 4) << 3) + (lane & 7)) * SA
                                        + (((lane >> 3) & 1) << 3)) * 2);
    const unsigned aS0 = sb + B_QHI + (unsigned)((mq * 32) * SA * 2) + a_lane;
    const unsigned aS1 = aS0 + (unsigned)(16 * SA * 2);
    const unsigned bS0 = sb + B_KHI + (unsigned)((nq * 32) * SA * 2) + b_lane;
    const unsigned bS1 = bS0 + (unsigned)(16 * SA * 2);

    for (int kb = 0; kb < Nn / NB; kb++) {
        __syncthreads();
        {
            const float* kp  = k  + bND + (size_t)(kb * NB) * Dn;
            const float* ksp = ks + bND + (size_t)(kb * NB) * Dn;
            #pragma unroll
            for (int it = 0; it < 8; it++) {
                int idx = (tid + it * THREADS) * 4;
                float4 a = *(const float4*)(kp + idx);
                float4 s0 = *(const float4*)(ksp + idx);
                a.x += s0.x; a.y += s0.y; a.z += s0.z; a.w += s0.w;
                int r = idx >> 6, d = idx & 63;
                unsigned h0, h1, l0, l1; split4(a, h0, h1, l0, l1);
                char* p = smb + B_KHI + (r * SA + d) * 2;
                *(uint2*)p = make_uint2(h0, h1);
                *(uint2*)(p + (B_KLO - B_KHI)) = make_uint2(l0, l1);
            }
        }
        __syncthreads();

        float acc[2][4][4];
        #pragma unroll
        for (int mf = 0; mf < 2; mf++)
            #pragma unroll
            for (int nf = 0; nf < 4; nf++)
                #pragma unroll
                for (int i = 0; i < 4; i++) acc[mf][nf][i] = 0.f;

        #pragma unroll
        for (int ksi = 0; ksi < 4; ksi++) {
            const unsigned ko = (unsigned)(ksi * 32);
            unsigned ah[2][4], al[2][4], bh[8], bl[8];
            ldsm4(ah[0], aS0 + ko);
            ldsm4(ah[1], aS1 + ko);
            ldsm4(al[0], aS0 + ko + (B_QLO - B_QHI));
            ldsm4(al[1], aS1 + ko + (B_QLO - B_QHI));
            ldsm4(bh,     bS0 + ko);
            ldsm4(bh + 4, bS1 + ko);
            ldsm4(bl,     bS0 + ko + (B_KLO - B_KHI));
            ldsm4(bl + 4, bS1 + ko + (B_KLO - B_KHI));
            #pragma unroll
            for (int nf = 0; nf < 4; nf++) {
                #pragma unroll
                for (int mf = 0; mf < 2; mf++) {
                    mma16816(acc[mf][nf], ah[mf], bh + nf * 2);
                    mma16816(acc[mf][nf], ah[mf], bl + nf * 2);
                    mma16816(acc[mf][nf], al[mf], bh + nf * 2);
                }
            }
        }

        // epilogue: scale, accumulate exp-sums, write attn_score
        #pragma unroll
        for (int mf = 0; mf < 2; mf++) {
            #pragma unroll
            for (int nf = 0; nf < 4; nf++) {
                float v0 = acc[mf][nf][0] * 0.125f;
                float v1 = acc[mf][nf][1] * 0.125f;
                float v2 = acc[mf][nf][2] * 0.125f;
                float v3 = acc[mf][nf][3] * 0.125f;
                sreg[mf * 2 + 0] += __expf(v0) + __expf(v1);
                sreg[mf * 2 + 1] += __expf(v2) + __expf(v3);
                const int r0 = row0 + mq * 32 + mf * 16 + lq;
                const int cc = kb * NB + nq * 32 + nf * 8 + lr * 2;
                float* g0 = score + bNN + (size_t)r0 * Nn + cc;
                *(float2*)g0 = make_float2(v0, v1);
                *(float2*)(g0 + (size_t)8 * Nn) = make_float2(v2, v3);
            }
        }
    }

    // combine partial sums (4 n-warps per row)
    #pragma unroll
    for (int i = 0; i < 4; i++) {
        sreg[i] += __shfl_xor_sync(0xffffffffu, sreg[i], 1);
        sreg[i] += __shfl_xor_sync(0xffffffffu, sreg[i], 2);
    }
    if (lr == 0) {
        #pragma unroll
        for (int mf = 0; mf < 2; mf++)
            #pragma unroll
            for (int hh = 0; hh < 2; hh++)
                spart[nq * 64 + mq * 32 + mf * 16 + hh * 8 + lq] = sreg[mf * 2 + hh];
    }
    __syncthreads();
    if (tid < 64)
        sinv[tid] = 1.0f / (spart[tid] + spart[64 + tid] + spart[128 + tid] + spart[192 + tid]);

    // ================= Pass PV: O = P @ V =================
    const int mq2 = wid >> 1;     // 0..3
    const int nq2 = wid & 1;      // 0..1
    float oacc[4][4];
    #pragma unroll
    for (int nf = 0; nf < 4; nf++)
        #pragma unroll
        for (int i = 0; i < 4; i++) oacc[nf][i] = 0.f;

    const unsigned ap_lane = (unsigned)(((lane & 15) * SP + (lane >> 4) * 8) * 2);
    const unsigned aP = sb + C_PHI + (unsigned)((mq2 * 16) * SP * 2) + ap_lane;
    const unsigned vb_lane = (unsigned)(((lane & 15) * SA + (lane >> 4) * 8) * 2);
    const unsigned bV0 = sb + C_VTH + (unsigned)((nq2 * 32) * 2) + vb_lane;
    const unsigned bV1 = bV0 + 32;   // +16 d elements

    for (int kc = 0; kc < Nn / NB; kc++) {
        __syncthreads();
        // build P hi/lo [64][SP] + write attn
        {
            const int pr  = tid >> 2;
            const int pcb = (tid & 3) * 32;
            const float iv = sinv[pr];
            const float* srow = score + bNN + (size_t)(row0 + pr) * Nn + kc * NB + pcb;
            float* arow = attn + bNN + (size_t)(row0 + pr) * Nn + kc * NB + pcb;
            #pragma unroll
            for (int j = 0; j < 8; j++) {
                float4 x = *(const float4*)(srow + j * 4);
                float4 p;
                p.x = __expf(x.x) * iv; p.y = __expf(x.y) * iv;
                p.z = __expf(x.z) * iv; p.w = __expf(x.w) * iv;
                *(float4*)(arow + j * 4) = p;
                unsigned h0, h1, l0, l1; split4(p, h0, h1, l0, l1);
                char* pp = smb + C_PHI + (pr * SP + pcb + j * 4) * 2;
                *(uint2*)pp = make_uint2(h0, h1);
                *(uint2*)(pp + (C_PLO - C_PHI)) = make_uint2(l0, l1);
            }
        }
        // build V hi/lo natural [128 keys][SA d] (coalesced)
        {
            const int ky = tid >> 1;
            const int db = (tid & 1) * 32;
            const float* vp = v + bND + (size_t)(kc * NB + ky) * Dn + db;
            #pragma unroll
            for (int j = 0; j < 8; j++) {
                float4 x = *(const float4*)(vp + j * 4);
                unsigned h0, h1, l0, l1; split4(x, h0, h1, l0, l1);
                char* pv = smb + C_VTH + (ky * SA + db + j * 4) * 2;
                *(uint2*)pv = make_uint2(h0, h1);
                *(uint2*)(pv + (C_VTL - C_VTH)) = make_uint2(l0, l1);
            }
        }
        __syncthreads();

        #pragma unroll
        for (int ksi = 0; ksi < 8; ksi++) {
            const unsigned ko = (unsigned)(ksi * 32);            // A: +16 keys
            const unsigned kv = (unsigned)(ksi * 16 * SA * 2);   // B: +16 key rows
            unsigned ah[4], al[4], bh[8], bl[8];
            ldsm4(ah, aP + ko);
            ldsm4(al, aP + ko + (C_PLO - C_PHI));
            ldsm4t(bh,     bV0 + kv);
            ldsm4t(bh + 4, bV1 + kv);
            ldsm4t(bl,     bV0 + kv + (C_VTL - C_VTH));
            ldsm4t(bl + 4, bV1 + kv + (C_VTL - C_VTH));
            #pragma unroll
            for (int nf = 0; nf < 4; nf++) {
                mma16816(oacc[nf], ah, bh + nf * 2);
                mma16816(oacc[nf], ah, bl + nf * 2);
                mma16816(oacc[nf], al, bh + nf * 2);
            }
        }
    }

    // write O
    #pragma unroll
    for (int nf = 0; nf < 4; nf++) {
        const int r0 = row0 + mq2 * 16 + lq;
        const int c = nq2 * 32 + nf * 8 + lr * 2;
        float* o0 = out + bND + (size_t)r0 * Dn + c;
        *(float2*)o0 = make_float2(oacc[nf][0], oacc[nf][1]);
        *(float2*)(o0 + (size_t)8 * Dn) = make_float2(oacc[nf][2], oacc[nf][3]);
    }
}

extern "C" void kernel_launch(void* const* d_in, const int* in_sizes, int n_in,
                              void* d_out, int out_size) {
    const float* q  = (const float*)d_in[0];
    const float* k  = (const float*)d_in[1];
    const float* v  = (const float*)d_in[2];
    const float* qs = (const float*)d_in[3];
    const float* ks = (const float*)d_in[4];

    float* out   = (float*)d_out;
    float* attn  = out  + (size_t)Bn * Nn * Dn;
    float* score = attn + (size_t)Bn * Nn * Nn;

    cudaFuncSetAttribute(sdpa_hmma_kernel,
                         cudaFuncAttributeMaxDynamicSharedMemorySize, SM_TOTAL);

    dim3 grid(Nn / Mr, Bn);
    sdpa_hmma_kernel<<<grid, THREADS, SM_TOTAL>>>(q, k, v, qs, ks, out, attn, score);
}

// round 5
// speedup vs baseline: 2.0196x; 1.3133x over previous
#include <cuda_runtime.h>
#include <cuda_bf16.h>
#include <math.h>

#define Bn 64
#define Nn 1024
#define Dn 64
#define Mr 64          // query rows per CTA
#define NB 128         // key block
#define THREADS 256
#define SA 72          // elem stride for 64-col bf16 tiles (144B, mult of 16)

// ---- smem byte offsets ----
#define SM_SPART 0          // float[4][64]
#define SM_SINV  1024       // float[64]
#define Q_HI     2048       // 64*72*2 = 9216
#define Q_LO     11264
#define K_HI     20480      // 128*72*2 = 18432
#define K_LO     38912
#define V_HI     57344
#define V_LO     75776
#define SM_TOTAL 94208
// O-reduction overlay on K/V region after last kb: [4][64][68] floats = 69632 B
#define RED      K_HI
#define RSTR     68

__device__ __forceinline__ void mma16816(float* c, const unsigned* a, const unsigned* b) {
    asm volatile(
        "mma.sync.aligned.m16n8k16.row.col.f32.bf16.bf16.f32 "
        "{%0,%1,%2,%3}, {%4,%5,%6,%7}, {%8,%9}, {%0,%1,%2,%3};"
        : "+f"(c[0]), "+f"(c[1]), "+f"(c[2]), "+f"(c[3])
        : "r"(a[0]), "r"(a[1]), "r"(a[2]), "r"(a[3]), "r"(b[0]), "r"(b[1]));
}
__device__ __forceinline__ void ldsm4(unsigned* r, unsigned addr) {
    asm volatile("ldmatrix.sync.aligned.m8n8.x4.shared.b16 {%0,%1,%2,%3}, [%4];"
        : "=r"(r[0]), "=r"(r[1]), "=r"(r[2]), "=r"(r[3]) : "r"(addr));
}
__device__ __forceinline__ void ldsm4t(unsigned* r, unsigned addr) {
    asm volatile("ldmatrix.sync.aligned.m8n8.x4.trans.shared.b16 {%0,%1,%2,%3}, [%4];"
        : "=r"(r[0]), "=r"(r[1]), "=r"(r[2]), "=r"(r[3]) : "r"(addr));
}
__device__ __forceinline__ void split4(float4 a, unsigned& h0, unsigned& h1,
                                       unsigned& l0, unsigned& l1) {
    __nv_bfloat162 H0 = __floats2bfloat162_rn(a.x, a.y);
    __nv_bfloat162 H1 = __floats2bfloat162_rn(a.z, a.w);
    float2 f0 = __bfloat1622float2(H0);
    float2 f1 = __bfloat1622float2(H1);
    __nv_bfloat162 L0 = __floats2bfloat162_rn(a.x - f0.x, a.y - f0.y);
    __nv_bfloat162 L1 = __floats2bfloat162_rn(a.z - f1.x, a.w - f1.y);
    h0 = *(unsigned*)&H0; h1 = *(unsigned*)&H1;
    l0 = *(unsigned*)&L0; l1 = *(unsigned*)&L1;
}
__device__ __forceinline__ unsigned pack2(float a, float b, float& la, float& lb) {
    __nv_bfloat162 H = __floats2bfloat162_rn(a, b);
    float2 f = __bfloat1622float2(H);
    la = a - f.x; lb = b - f.y;
    return *(unsigned*)&H;
}

__global__ __launch_bounds__(THREADS, 2)
void sdpa_fused_kernel(const float* __restrict__ q,
                       const float* __restrict__ k,
                       const float* __restrict__ v,
                       const float* __restrict__ qs,
                       const float* __restrict__ ks,
                       float* __restrict__ out,
                       float* __restrict__ attn,
                       float* __restrict__ score)
{
    extern __shared__ char smb[];
    const unsigned sb = (unsigned)__cvta_generic_to_shared(smb);
    const int tid  = threadIdx.x;
    const int wid  = tid >> 5;
    const int lane = tid & 31;
    const int b    = blockIdx.y;
    const int row0 = blockIdx.x * Mr;
    const size_t bND = (size_t)b * Nn * Dn;
    const size_t bNN = (size_t)b * Nn * Nn;

    float* spart = (float*)(smb + SM_SPART);
    float* sinv  = (float*)(smb + SM_SINV);
    float* red   = (float*)(smb + RED);

    // ---- Q fill: Qf = q + q_sem -> bf16 hi/lo [64][SA] ----
    {
        const float* qp  = q  + bND + (size_t)row0 * Dn;
        const float* qsp = qs + bND + (size_t)row0 * Dn;
        #pragma unroll
        for (int it = 0; it < 4; it++) {
            int idx = (tid + it * THREADS) * 4;
            float4 a = *(const float4*)(qp + idx);
            float4 s0 = *(const float4*)(qsp + idx);
            a.x += s0.x; a.y += s0.y; a.z += s0.z; a.w += s0.w;
            int r = idx >> 6, d = idx & 63;
            unsigned h0, h1, l0, l1; split4(a, h0, h1, l0, l1);
            char* p = smb + Q_HI + (r * SA + d) * 2;
            *(uint2*)p = make_uint2(h0, h1);
            *(uint2*)(p + (Q_LO - Q_HI)) = make_uint2(l0, l1);
        }
    }

    const int mq = wid >> 2;   // 0..1
    const int nq = wid & 3;    // 0..3
    const int lq = lane >> 2;  // 0..7
    const int lr = lane & 3;   // 0..3
    float sreg[4] = {0.f, 0.f, 0.f, 0.f};
    float oacc[2][8][4];
    #pragma unroll
    for (int mf = 0; mf < 2; mf++)
        #pragma unroll
        for (int dn = 0; dn < 8; dn++)
            #pragma unroll
            for (int i = 0; i < 4; i++) oacc[mf][dn][i] = 0.f;

    const unsigned a_lane = (unsigned)(((lane & 15) * SA + (lane >> 4) * 8) * 2);
    const unsigned b_lane = (unsigned)(((((lane >> 4) << 3) + (lane & 7)) * SA
                                        + (((lane >> 3) & 1) << 3)) * 2);
    const unsigned aS0 = sb + Q_HI + (unsigned)((mq * 32) * SA * 2) + a_lane;
    const unsigned aS1 = aS0 + (unsigned)(16 * SA * 2);
    const unsigned vb_lane = (unsigned)(((lane & 15) * SA + (lane >> 4) * 8) * 2);

    for (int kb = 0; kb < Nn / NB; kb++) {
        __syncthreads();
        // fill Kf hi/lo and V hi/lo tiles [128][SA]
        {
            const float* kp  = k  + bND + (size_t)(kb * NB) * Dn;
            const float* ksp = ks + bND + (size_t)(kb * NB) * Dn;
            #pragma unroll
            for (int it = 0; it < 8; it++) {
                int idx = (tid + it * THREADS) * 4;
                float4 a = *(const float4*)(kp + idx);
                float4 s0 = *(const float4*)(ksp + idx);
                a.x += s0.x; a.y += s0.y; a.z += s0.z; a.w += s0.w;
                int r = idx >> 6, d = idx & 63;
                unsigned h0, h1, l0, l1; split4(a, h0, h1, l0, l1);
                char* p = smb + K_HI + (r * SA + d) * 2;
                *(uint2*)p = make_uint2(h0, h1);
                *(uint2*)(p + (K_LO - K_HI)) = make_uint2(l0, l1);
            }
            const int ky = tid >> 1;
            const int db = (tid & 1) * 32;
            const float* vp = v + bND + (size_t)(kb * NB + ky) * Dn + db;
            #pragma unroll
            for (int j = 0; j < 8; j++) {
                float4 x = *(const float4*)(vp + j * 4);
                unsigned h0, h1, l0, l1; split4(x, h0, h1, l0, l1);
                char* pv = smb + V_HI + (ky * SA + db + j * 4) * 2;
                *(uint2*)pv = make_uint2(h0, h1);
                *(uint2*)(pv + (V_LO - V_HI)) = make_uint2(l0, l1);
            }
        }
        __syncthreads();

        // two 16-col chunks of this warp's 32 score columns
        #pragma unroll
        for (int ch = 0; ch < 2; ch++) {
            const int colbase = nq * 32 + ch * 16;   // local key base
            float acc[2][2][4];
            #pragma unroll
            for (int mf = 0; mf < 2; mf++)
                #pragma unroll
                for (int nfl = 0; nfl < 2; nfl++)
                    #pragma unroll
                    for (int i = 0; i < 4; i++) acc[mf][nfl][i] = 0.f;

            const unsigned bS = sb + K_HI + (unsigned)(colbase * SA * 2) + b_lane;
            #pragma unroll
            for (int ksi = 0; ksi < 4; ksi++) {
                const unsigned ko = (unsigned)(ksi * 32);
                unsigned ah[2][4], al[2][4], bh[4], bl[4];
                ldsm4(ah[0], aS0 + ko);
                ldsm4(ah[1], aS1 + ko);
                ldsm4(al[0], aS0 + ko + (Q_LO - Q_HI));
                ldsm4(al[1], aS1 + ko + (Q_LO - Q_HI));
                ldsm4(bh, bS + ko);
                ldsm4(bl, bS + ko + (K_LO - K_HI));
                #pragma unroll
                for (int nfl = 0; nfl < 2; nfl++)
                    #pragma unroll
                    for (int mf = 0; mf < 2; mf++) {
                        mma16816(acc[mf][nfl], ah[mf], bh + nfl * 2);
                        mma16816(acc[mf][nfl], ah[mf], bl + nfl * 2);
                        mma16816(acc[mf][nfl], al[mf], bh + nfl * 2);
                    }
            }

            // epilogue: score out + E frags (A of PV) in regs
            unsigned ahv[2][4], alv[2][4];
            #pragma unroll
            for (int mf = 0; mf < 2; mf++) {
                #pragma unroll
                for (int nfl = 0; nfl < 2; nfl++) {
                    float v0 = acc[mf][nfl][0] * 0.125f;
                    float v1 = acc[mf][nfl][1] * 0.125f;
                    float v2 = acc[mf][nfl][2] * 0.125f;
                    float v3 = acc[mf][nfl][3] * 0.125f;
                    const int r0 = row0 + mq * 32 + mf * 16 + lq;
                    const int cc = kb * NB + colbase + nfl * 8 + lr * 2;
                    float* g0 = score + bNN + (size_t)r0 * Nn + cc;
                    *(float2*)g0 = make_float2(v0, v1);
                    *(float2*)(g0 + (size_t)8 * Nn) = make_float2(v2, v3);
                    float e0 = __expf(v0), e1 = __expf(v1);
                    float e2 = __expf(v2), e3 = __expf(v3);
                    sreg[mf * 2 + 0] += e0 + e1;
                    sreg[mf * 2 + 1] += e2 + e3;
                    float la, lb;
                    ahv[mf][nfl * 2 + 0] = pack2(e0, e1, la, lb);
                    __nv_bfloat162 L = __floats2bfloat162_rn(la, lb);
                    alv[mf][nfl * 2 + 0] = *(unsigned*)&L;
                    ahv[mf][nfl * 2 + 1] = pack2(e2, e3, la, lb);
                    L = __floats2bfloat162_rn(la, lb);
                    alv[mf][nfl * 2 + 1] = *(unsigned*)&L;
                }
            }

            // PV: k16 = this chunk's 16 keys, over all 64 d-cols
            const unsigned bVb = sb + V_HI + (unsigned)(colbase * SA * 2) + vb_lane;
            #pragma unroll
            for (int dn = 0; dn < 4; dn++) {      // 16 d-cols per iter
                unsigned bh[4], bl[4];
                ldsm4t(bh, bVb + dn * 32);
                ldsm4t(bl, bVb + dn * 32 + (V_LO - V_HI));
                #pragma unroll
                for (int h = 0; h < 2; h++)
                    #pragma unroll
                    for (int mf = 0; mf < 2; mf++) {
                        mma16816(oacc[mf][dn * 2 + h], ahv[mf], bh + h * 2);
                        mma16816(oacc[mf][dn * 2 + h], alv[mf], bh + h * 2);
                        mma16816(oacc[mf][dn * 2 + h], ahv[mf], bl + h * 2);
                    }
            }
        }
    }

    // ---- combine row sums + stage partial O ----
    #pragma unroll
    for (int i = 0; i < 4; i++) {
        sreg[i] += __shfl_xor_sync(0xffffffffu, sreg[i], 1);
        sreg[i] += __shfl_xor_sync(0xffffffffu, sreg[i], 2);
    }
    __syncthreads();   // all warps done reading K/V smem -> safe to overlay
    if (lr == 0) {
        #pragma unroll
        for (int mf = 0; mf < 2; mf++)
            #pragma unroll
            for (int hh = 0; hh < 2; hh++)
                spart[nq * 64 + mq * 32 + mf * 16 + hh * 8 + lq] = sreg[mf * 2 + hh];
    }
    #pragma unroll
    for (int mf = 0; mf < 2; mf++) {
        const int rl = mq * 32 + mf * 16 + lq;
        #pragma unroll
        for (int dn = 0; dn < 8; dn++) {
            const int cl = dn * 8 + 2 * lr;
            float* p0 = red + ((size_t)nq * 64 + rl) * RSTR + cl;
            *(float2*)p0 = make_float2(oacc[mf][dn][0], oacc[mf][dn][1]);
            *(float2*)(p0 + 8 * RSTR) = make_float2(oacc[mf][dn][2], oacc[mf][dn][3]);
        }
    }
    __syncthreads();

    // ---- reduce 4 slices, scale by 1/rowsum, write O; also publish sinv ----
    {
        const int r = tid >> 2;
        const int cb = (tid & 3) * 16;
        const float iv = 1.0f / (spart[r] + spart[64 + r] + spart[128 + r] + spart[192 + r]);
        if ((tid & 3) == 0) sinv[r] = iv;
        float* orow = out + bND + (size_t)(row0 + r) * Dn;
        #pragma unroll
        for (int g = 0; g < 4; g++) {
            const int c = cb + g * 4;
            float4 s0 = *(float4*)(red + (size_t)r * RSTR + c);
            float4 s1 = *(float4*)(red + ((size_t)64 + r) * RSTR + c);
            float4 s2 = *(float4*)(red + ((size_t)128 + r) * RSTR + c);
            float4 s3 = *(float4*)(red + ((size_t)192 + r) * RSTR + c);
            float4 o;
            o.x = (s0.x + s1.x + s2.x + s3.x) * iv;
            o.y = (s0.y + s1.y + s2.y + s3.y) * iv;
            o.z = (s0.z + s1.z + s2.z + s3.z) * iv;
            o.w = (s0.w + s1.w + s2.w + s3.w) * iv;
            *(float4*)(orow + c) = o;
        }
    }
    __syncthreads();

    // ---- coalesced attn rescale: attn = exp(score) * inv ----
    #pragma unroll
    for (int rr = 0; rr < 8; rr++) {
        const int r = rr * 8 + wid;
        const float iv = sinv[r];
        const float* srow = score + bNN + (size_t)(row0 + r) * Nn;
        float* arow = attn + bNN + (size_t)(row0 + r) * Nn;
        #pragma unroll
        for (int j = 0; j < 8; j++) {
            float4 x = *(const float4*)(srow + j * 128 + lane * 4);
            float4 p;
            p.x = __expf(x.x) * iv; p.y = __expf(x.y) * iv;
            p.z = __expf(x.z) * iv; p.w = __expf(x.w) * iv;
            *(float4*)(arow + j * 128 + lane * 4) = p;
        }
    }
}

extern "C" void kernel_launch(void* const* d_in, const int* in_sizes, int n_in,
                              void* d_out, int out_size) {
    const float* q  = (const float*)d_in[0];
    const float* k  = (const float*)d_in[1];
    const float* v  = (const float*)d_in[2];
    const float* qs = (const float*)d_in[3];
    const float* ks = (const float*)d_in[4];

    float* out   = (float*)d_out;
    float* attn  = out  + (size_t)Bn * Nn * Dn;
    float* score = attn + (size_t)Bn * Nn * Nn;

    cudaFuncSetAttribute(sdpa_fused_kernel,
                         cudaFuncAttributeMaxDynamicSharedMemorySize, SM_TOTAL);

    dim3 grid(Nn / Mr, Bn);
    sdpa_fused_kernel<<<grid, THREADS, SM_TOTAL>>>(q, k, v, qs, ks, out, attn, score);
}